// round 15
// baseline (speedup 1.0000x reference)
#include <cuda_runtime.h>
#include <cuda_fp16.h>

#define N_NODES 100000
#define N_EDGES 1600000
#define F 64
#define SCAN_B 512
#define N_SCANB ((N_NODES + SCAN_B - 1) / SCAN_B)   // 196
#define NA 50048                                     // pipeline split (782*64)

// ---- scratch (static __device__, zero-initialized at module load; each call
//      restores the zeros it consumes -> invariant holds across graph replays)
__device__ int     g_done;                 // scan completion counter (self-resetting)
__device__ int     g_indeg[N_NODES];       // re-zeroed by k_aggregate<1> after last use
__device__ int     g_start[N_NODES];
__device__ int     g_cur[N_NODES];
__device__ int     g_bsum[SCAN_B];
__device__ int     g_boff[SCAN_B];
__device__ float   g_dinv[N_NODES];
__device__ int     g_csr[N_EDGES];
__device__ __half2 g_hsh [N_NODES * 32];   // layer-1 messages
__device__ __half2 g_hsh2[N_NODES * 32];   // layer-2 messages (double buffer!)
__device__ float   g_z[N_NODES * F];

// ---------------------------------------------------------------------------
__global__ void k_count(const int* __restrict__ ei) {
    int e = blockIdx.x * blockDim.x + threadIdx.x;
    if (e >= N_EDGES) return;
    int d = ei[N_EDGES + e];
    if ((unsigned)d < N_NODES) atomicAdd(&g_indeg[d], 1);
}

// ---------------------------------------------------------------------------
// Shuffle-based inclusive block scan (512 threads).
// ---------------------------------------------------------------------------
__device__ __forceinline__ int block_scan_incl(int v, int tid, int* warpsum) {
    const int lane = tid & 31, w = tid >> 5;
    int x = v;
    #pragma unroll
    for (int s = 1; s < 32; s <<= 1) {
        int t = __shfl_up_sync(0xffffffff, x, s);
        if (lane >= s) x += t;
    }
    if (lane == 31) warpsum[w] = x;
    __syncthreads();
    if (w == 0) {
        int y = (lane < 16) ? warpsum[lane] : 0;
        #pragma unroll
        for (int s = 1; s < 16; s <<= 1) {
            int t = __shfl_up_sync(0xffffffff, y, s);
            if (lane >= s) y += t;
        }
        if (lane < 16) warpsum[lane] = y;
    }
    __syncthreads();
    return x + (w > 0 ? warpsum[w - 1] : 0);
}

__global__ void __launch_bounds__(SCAN_B) k_scan() {
    __shared__ int ws[16];
    __shared__ int amLast;
    const int tid = threadIdx.x;
    int i = blockIdx.x * SCAN_B + tid;
    int v = (i < N_NODES) ? g_indeg[i] : 0;
    int incl = block_scan_incl(v, tid, ws);
    if (i < N_NODES) {
        int ex = incl - v;
        g_start[i] = ex;
        g_cur[i]   = ex;
        g_dinv[i]  = rsqrtf((float)(v + 1));   // +1 self loop
    }
    if (tid == SCAN_B - 1) g_bsum[blockIdx.x] = incl;
    __threadfence();
    __syncthreads();
    if (tid == 0)
        amLast = (atomicAdd(&g_done, 1) == (int)gridDim.x - 1);
    __syncthreads();
    if (amLast) {
        __threadfence();
        int bv = (tid < N_SCANB) ? g_bsum[tid] : 0;
        int bincl = block_scan_incl(bv, tid, ws);
        if (tid < N_SCANB) g_boff[tid] = bincl - bv;
        if (tid == 0) g_done = 0;   // restore invariant for next call
    }
}

__global__ void k_fill(const int* __restrict__ ei) {
    int e = blockIdx.x * blockDim.x + threadIdx.x;
    if (e >= N_EDGES) return;
    int s = ei[e];
    int d = ei[N_EDGES + e];
    if ((unsigned)s < N_NODES && (unsigned)d < N_NODES) {
        int slot = atomicAdd(&g_cur[d], 1) + g_boff[d >> 9];
        if ((unsigned)slot < N_EDGES) g_csr[slot] = s;
    }
}

// ---------------------------------------------------------------------------
// Per-node scale pass: g_hsh[row] *= dinv[row]; overlapped with k_fill on s2.
// ---------------------------------------------------------------------------
__global__ void __launch_bounds__(256) k_scale() {
    int i = blockIdx.x * blockDim.x + threadIdx.x;          // uint4 index
    if (i >= N_NODES * 8) return;
    int row = i >> 3;
    __half2 dh = __float2half2_rn(g_dinv[row]);
    uint4 v = *(const uint4*)&g_hsh[(size_t)i * 4];
    __half2* p = (__half2*)&v;
    p[0] = __hmul2(p[0], dh);
    p[1] = __hmul2(p[1], dh);
    p[2] = __hmul2(p[2], dh);
    p[3] = __hmul2(p[3], dh);
    *(uint4*)&g_hsh[(size_t)i * 4] = v;
}

// ---------------------------------------------------------------------------
// Tensor-core GEMM (tf32 m16n8k8), fp16 store. row0 = chunk base row.
//   L == 0: X = raw h -> g_hsh, raw product (no dinv; forked at t=0).
//   L == 1: X = g_z  -> g_hsh2, dinv epilogue.   (separate buffers => the
//           agg0 || gemm1 pipeline has no WAR hazard)
// ---------------------------------------------------------------------------
#define XP 68
#define WP 72

__device__ __forceinline__ unsigned f2tf32(float f) {
    unsigned r;
    asm("cvt.rna.tf32.f32 %0, %1;" : "=r"(r) : "f"(f));
    return r;
}

template <int L>
__global__ void __launch_bounds__(256) k_gemm(const float* __restrict__ Xin,
                                              const float* __restrict__ W,
                                              int row0) {
    __shared__ unsigned Xs[64 * XP];
    __shared__ unsigned Ws[64 * WP];

    const float* __restrict__ X = (L == 0) ? Xin : (const float*)g_z;
    __half2* __restrict__ dst = (L == 0) ? g_hsh : g_hsh2;

    const int tid = threadIdx.x;
    const int rowbase = row0 + blockIdx.x * 64;

    #pragma unroll
    for (int i = tid; i < 64 * 64; i += 256) {
        int k = i >> 6, n = i & 63;
        Ws[k * WP + n] = f2tf32(W[i]);
    }
    #pragma unroll
    for (int i = tid; i < 64 * 64; i += 256) {
        int r = i >> 6, c = i & 63;
        int row = rowbase + r;
        float v = (row < N_NODES) ? X[row * 64 + c] : 0.0f;
        Xs[r * XP + c] = f2tf32(v);
    }
    __syncthreads();

    const int warp = tid >> 5;
    const int lane = tid & 31;
    const int gid  = lane >> 2;
    const int tg   = lane & 3;
    const int wr   = (warp & 3) * 16;
    const int wc   = (warp >> 2) * 32;

    float4 acc[4] = {{0,0,0,0},{0,0,0,0},{0,0,0,0},{0,0,0,0}};

    #pragma unroll
    for (int kb = 0; kb < 64; kb += 8) {
        const unsigned* xrow = &Xs[(wr + gid) * XP + kb + tg];
        unsigned a0 = xrow[0];
        unsigned a1 = xrow[8 * XP];
        unsigned a2 = xrow[4];
        unsigned a3 = xrow[8 * XP + 4];
        #pragma unroll
        for (int t = 0; t < 4; t++) {
            const unsigned* wcol = &Ws[(kb + tg) * WP + wc + t * 8 + gid];
            unsigned b0 = wcol[0];
            unsigned b1 = wcol[4 * WP];
            asm volatile(
                "mma.sync.aligned.m16n8k8.row.col.f32.tf32.tf32.f32 "
                "{%0,%1,%2,%3}, {%4,%5,%6,%7}, {%8,%9}, {%0,%1,%2,%3};"
                : "+f"(acc[t].x), "+f"(acc[t].y), "+f"(acc[t].z), "+f"(acc[t].w)
                : "r"(a0), "r"(a1), "r"(a2), "r"(a3), "r"(b0), "r"(b1));
        }
    }

    const int r0 = rowbase + wr + gid;
    const int r1 = r0 + 8;
    float d0 = 1.0f, d1 = 1.0f;
    if (L == 1) {
        d0 = (r0 < N_NODES) ? g_dinv[r0] : 0.0f;
        d1 = (r1 < N_NODES) ? g_dinv[r1] : 0.0f;
    }
    #pragma unroll
    for (int t = 0; t < 4; t++) {
        int slot = (wc >> 1) + t * 4 + tg;
        if (r0 < N_NODES)
            dst[r0 * 32 + slot] = __floats2half2_rn(acc[t].x * d0, acc[t].y * d0);
        if (r1 < N_NODES)
            dst[r1 * 32 + slot] = __floats2half2_rn(acc[t].z * d1, acc[t].w * d1);
    }
}

// ---------------------------------------------------------------------------
// z[node] = relu( dinv[node] * (hs[node] + sum_{neigh} hs[s]) + b )
// FUSE_OUT == 0: reads g_hsh, writes g_z.
// FUSE_OUT == 1: reads g_hsh2, fused linear readout, restores indeg invariant.
// ---------------------------------------------------------------------------
template <int FUSE_OUT>
__global__ void __launch_bounds__(256) k_aggregate(const float* __restrict__ b,
                                                   const float* __restrict__ Wo,
                                                   const float* __restrict__ bo,
                                                   float* __restrict__ out,
                                                   int node0, int node1) {
    const int t = blockIdx.x * blockDim.x + threadIdx.x;
    const int node = node0 + (t >> 5);
    if (node >= node1) return;
    const int lane = t & 31;

    const __half2* __restrict__ hs = (FUSE_OUT == 0) ? g_hsh : g_hsh2;

    float2 acc = __half22float2(hs[node * 32 + lane]);  // self loop

    const int deg = g_indeg[node];
    int e   = g_start[node] + g_boff[node >> 9];
    const int end = e + deg;

    for (; e + 8 <= end; e += 8) {
        int s0 = __ldg(&g_csr[e]);
        int s1 = __ldg(&g_csr[e + 1]);
        int s2 = __ldg(&g_csr[e + 2]);
        int s3 = __ldg(&g_csr[e + 3]);
        int s4 = __ldg(&g_csr[e + 4]);
        int s5 = __ldg(&g_csr[e + 5]);
        int s6 = __ldg(&g_csr[e + 6]);
        int s7 = __ldg(&g_csr[e + 7]);
        float2 v0 = __half22float2(__ldg(&hs[s0 * 32 + lane]));
        float2 v1 = __half22float2(__ldg(&hs[s1 * 32 + lane]));
        float2 v2 = __half22float2(__ldg(&hs[s2 * 32 + lane]));
        float2 v3 = __half22float2(__ldg(&hs[s3 * 32 + lane]));
        float2 v4 = __half22float2(__ldg(&hs[s4 * 32 + lane]));
        float2 v5 = __half22float2(__ldg(&hs[s5 * 32 + lane]));
        float2 v6 = __half22float2(__ldg(&hs[s6 * 32 + lane]));
        float2 v7 = __half22float2(__ldg(&hs[s7 * 32 + lane]));
        acc.x += ((v0.x + v1.x) + (v2.x + v3.x)) + ((v4.x + v5.x) + (v6.x + v7.x));
        acc.y += ((v0.y + v1.y) + (v2.y + v3.y)) + ((v4.y + v5.y) + (v6.y + v7.y));
    }
    for (; e < end; e++) {
        int s = __ldg(&g_csr[e]);
        float2 v = __half22float2(__ldg(&hs[s * 32 + lane]));
        acc.x += v.x; acc.y += v.y;
    }

    const float di = g_dinv[node];
    const int c = lane * 2;
    float2 bb = *(const float2*)(b + c);
    float zx = fmaxf(acc.x * di + bb.x, 0.0f);
    float zy = fmaxf(acc.y * di + bb.y, 0.0f);

    if constexpr (FUSE_OUT == 0) {
        *(float2*)(g_z + node * 64 + c) = make_float2(zx, zy);
    } else {
        float2 w = *(const float2*)(Wo + c);
        float sum = zx * w.x + zy * w.y;
        #pragma unroll
        for (int off = 16; off; off >>= 1)
            sum += __shfl_down_sync(0xffffffff, sum, off);
        if (lane == 0) {
            out[node] = sum + bo[0];
            g_indeg[node] = 0;       // restore invariant for next call
        }
    }
}

// ---------------------------------------------------------------------------
extern "C" void kernel_launch(void* const* d_in, const int* in_sizes, int n_in,
                              void* d_out, int out_size) {
    const float* h  = (const float*)d_in[0];
    const int*   ei = (const int*)d_in[1];   // int32 [2,E]
    const float* W1 = (const float*)d_in[2];
    const float* b1 = (const float*)d_in[3];
    const float* W2 = (const float*)d_in[4];
    const float* b2 = (const float*)d_in[5];
    const float* Wo = (const float*)d_in[6];
    const float* bo = (const float*)d_in[7];
    float* out = (float*)d_out;

    cudaStream_t s2;
    cudaStreamCreateWithFlags(&s2, cudaStreamNonBlocking);
    cudaEvent_t eFork, eScan, eJoin, eA, eG;
    cudaEventCreateWithFlags(&eFork, cudaEventDisableTiming);
    cudaEventCreateWithFlags(&eScan, cudaEventDisableTiming);
    cudaEventCreateWithFlags(&eJoin, cudaEventDisableTiming);
    cudaEventCreateWithFlags(&eA, cudaEventDisableTiming);
    cudaEventCreateWithFlags(&eG, cudaEventDisableTiming);

    // s2: gemm0 (raw h@W1, zero deps) at t=0.
    cudaEventRecord(eFork, 0);
    cudaStreamWaitEvent(s2, eFork, 0);
    k_gemm<0><<<(N_NODES + 63) / 64, 256, 0, s2>>>(h, W1, 0);

    // main: CSR build (no init kernel — invariant maintained by consumers).
    k_count<<<(N_EDGES + 255) / 256, 256>>>(ei);
    k_scan<<<N_SCANB, SCAN_B>>>();
    cudaEventRecord(eScan, 0);

    // s2: scale pass (after gemm0 in-stream + scan's dinv); overlaps k_fill.
    cudaStreamWaitEvent(s2, eScan, 0);
    k_scale<<<(N_NODES * 8 + 255) / 256, 256, 0, s2>>>();
    cudaEventRecord(eJoin, s2);

    k_fill<<<(N_EDGES + 255) / 256, 256>>>(ei);

    // Pipelined layer-1 conv + layer-2 transform (double-buffered: gemm1
    // writes g_hsh2, agg0 reads g_hsh -> no WAR hazard).
    cudaStreamWaitEvent(0, eJoin, 0);
    k_aggregate<0><<<(NA * 32 + 255) / 256, 256>>>(b1, nullptr, nullptr, nullptr, 0, NA);
    cudaEventRecord(eA, 0);

    cudaStreamWaitEvent(s2, eA, 0);
    k_gemm<1><<<NA / 64, 256, 0, s2>>>(nullptr, W2, 0);            // rows [0, NA)
    cudaEventRecord(eG, s2);

    k_aggregate<0><<<((N_NODES - NA) * 32 + 255) / 256, 256>>>(b1, nullptr, nullptr, nullptr, NA, N_NODES);
    k_gemm<1><<<(N_NODES - NA + 63) / 64, 256>>>(nullptr, W2, NA); // rows [NA, N)

    cudaStreamWaitEvent(0, eG, 0);
    k_aggregate<1><<<(N_NODES * 32 + 255) / 256, 256>>>(b2, Wo, bo, out, 0, N_NODES);

    cudaEventDestroy(eFork);
    cudaEventDestroy(eScan);
    cudaEventDestroy(eJoin);
    cudaEventDestroy(eA);
    cudaEventDestroy(eG);
    cudaStreamDestroy(s2);
}

// round 16
// speedup vs baseline: 1.0343x; 1.0343x over previous
#include <cuda_runtime.h>
#include <cuda_fp16.h>

#define N_NODES 100000
#define N_EDGES 1600000
#define F 64
#define SCAN_B 512
#define N_SCANB ((N_NODES + SCAN_B - 1) / SCAN_B)   // 196

// ---- scratch (static __device__, zero-initialized at module load; each call
//      restores the zeros it consumes -> invariant holds across graph replays)
__device__ int     g_done;                 // scan completion counter (self-resetting)
__device__ int     g_indeg[N_NODES];       // re-zeroed by k_aggregate<1> after last use
__device__ int     g_start[N_NODES];
__device__ int     g_cur[N_NODES];
__device__ int     g_bsum[SCAN_B];
__device__ int     g_boff[SCAN_B];
__device__ float   g_dinv[N_NODES];
__device__ int     g_csr[N_EDGES];
__device__ __half2 g_hsh [N_NODES * 32];   // layer-1 messages
__device__ __half2 g_hsh2[N_NODES * 32];   // layer-2 messages
__device__ float   g_z[N_NODES * F];

// ---------------------------------------------------------------------------
__global__ void k_count(const int* __restrict__ ei) {
    int e = blockIdx.x * blockDim.x + threadIdx.x;
    if (e >= N_EDGES) return;
    int d = ei[N_EDGES + e];
    if ((unsigned)d < N_NODES) atomicAdd(&g_indeg[d], 1);
}

// ---------------------------------------------------------------------------
// Shuffle-based inclusive block scan (512 threads).
// ---------------------------------------------------------------------------
__device__ __forceinline__ int block_scan_incl(int v, int tid, int* warpsum) {
    const int lane = tid & 31, w = tid >> 5;
    int x = v;
    #pragma unroll
    for (int s = 1; s < 32; s <<= 1) {
        int t = __shfl_up_sync(0xffffffff, x, s);
        if (lane >= s) x += t;
    }
    if (lane == 31) warpsum[w] = x;
    __syncthreads();
    if (w == 0) {
        int y = (lane < 16) ? warpsum[lane] : 0;
        #pragma unroll
        for (int s = 1; s < 16; s <<= 1) {
            int t = __shfl_up_sync(0xffffffff, y, s);
            if (lane >= s) y += t;
        }
        if (lane < 16) warpsum[lane] = y;
    }
    __syncthreads();
    return x + (w > 0 ? warpsum[w - 1] : 0);
}

__global__ void __launch_bounds__(SCAN_B) k_scan() {
    __shared__ int ws[16];
    __shared__ int amLast;
    const int tid = threadIdx.x;
    int i = blockIdx.x * SCAN_B + tid;
    int v = (i < N_NODES) ? g_indeg[i] : 0;
    int incl = block_scan_incl(v, tid, ws);
    if (i < N_NODES) {
        int ex = incl - v;
        g_start[i] = ex;
        g_cur[i]   = ex;
        g_dinv[i]  = rsqrtf((float)(v + 1));   // +1 self loop
    }
    if (tid == SCAN_B - 1) g_bsum[blockIdx.x] = incl;
    __threadfence();
    __syncthreads();
    if (tid == 0)
        amLast = (atomicAdd(&g_done, 1) == (int)gridDim.x - 1);
    __syncthreads();
    if (amLast) {
        __threadfence();
        int bv = (tid < N_SCANB) ? g_bsum[tid] : 0;
        int bincl = block_scan_incl(bv, tid, ws);
        if (tid < N_SCANB) g_boff[tid] = bincl - bv;
        if (tid == 0) g_done = 0;   // restore invariant for next call
    }
}

__global__ void k_fill(const int* __restrict__ ei) {
    int e = blockIdx.x * blockDim.x + threadIdx.x;
    if (e >= N_EDGES) return;
    int s = ei[e];
    int d = ei[N_EDGES + e];
    if ((unsigned)s < N_NODES && (unsigned)d < N_NODES) {
        int slot = atomicAdd(&g_cur[d], 1) + g_boff[d >> 9];
        if ((unsigned)slot < N_EDGES) g_csr[slot] = s;
    }
}

// ---------------------------------------------------------------------------
// Per-node scale pass: g_hsh[row] *= dinv[row]; overlapped with k_fill on s2.
// ---------------------------------------------------------------------------
__global__ void __launch_bounds__(256) k_scale() {
    int i = blockIdx.x * blockDim.x + threadIdx.x;          // uint4 index
    if (i >= N_NODES * 8) return;
    int row = i >> 3;
    __half2 dh = __float2half2_rn(g_dinv[row]);
    uint4 v = *(const uint4*)&g_hsh[(size_t)i * 4];
    __half2* p = (__half2*)&v;
    p[0] = __hmul2(p[0], dh);
    p[1] = __hmul2(p[1], dh);
    p[2] = __hmul2(p[2], dh);
    p[3] = __hmul2(p[3], dh);
    *(uint4*)&g_hsh[(size_t)i * 4] = v;
}

// ---------------------------------------------------------------------------
// Tensor-core GEMM (tf32 m16n8k8), fp16 store.
//   L == 0: X = raw h -> g_hsh, raw product (no dinv; forked at t=0).
//   L == 1: X = g_z  -> g_hsh2, dinv epilogue.
// 64x64 tile, 256 threads = 8 warps. Pitches: Xs 68, Ws 72 (conflict-free).
// ---------------------------------------------------------------------------
#define XP 68
#define WP 72

__device__ __forceinline__ unsigned f2tf32(float f) {
    unsigned r;
    asm("cvt.rna.tf32.f32 %0, %1;" : "=r"(r) : "f"(f));
    return r;
}

template <int L>
__global__ void __launch_bounds__(256) k_gemm(const float* __restrict__ Xin,
                                              const float* __restrict__ W) {
    __shared__ unsigned Xs[64 * XP];
    __shared__ unsigned Ws[64 * WP];

    const float* __restrict__ X = (L == 0) ? Xin : (const float*)g_z;
    __half2* __restrict__ dst = (L == 0) ? g_hsh : g_hsh2;

    const int tid = threadIdx.x;
    const int rowbase = blockIdx.x * 64;

    #pragma unroll
    for (int i = tid; i < 64 * 64; i += 256) {
        int k = i >> 6, n = i & 63;
        Ws[k * WP + n] = f2tf32(W[i]);
    }
    #pragma unroll
    for (int i = tid; i < 64 * 64; i += 256) {
        int r = i >> 6, c = i & 63;
        int row = rowbase + r;
        float v = (row < N_NODES) ? X[row * 64 + c] : 0.0f;
        Xs[r * XP + c] = f2tf32(v);
    }
    __syncthreads();

    const int warp = tid >> 5;
    const int lane = tid & 31;
    const int gid  = lane >> 2;
    const int tg   = lane & 3;
    const int wr   = (warp & 3) * 16;
    const int wc   = (warp >> 2) * 32;

    float4 acc[4] = {{0,0,0,0},{0,0,0,0},{0,0,0,0},{0,0,0,0}};

    #pragma unroll
    for (int kb = 0; kb < 64; kb += 8) {
        const unsigned* xrow = &Xs[(wr + gid) * XP + kb + tg];
        unsigned a0 = xrow[0];
        unsigned a1 = xrow[8 * XP];
        unsigned a2 = xrow[4];
        unsigned a3 = xrow[8 * XP + 4];
        #pragma unroll
        for (int t = 0; t < 4; t++) {
            const unsigned* wcol = &Ws[(kb + tg) * WP + wc + t * 8 + gid];
            unsigned b0 = wcol[0];
            unsigned b1 = wcol[4 * WP];
            asm volatile(
                "mma.sync.aligned.m16n8k8.row.col.f32.tf32.tf32.f32 "
                "{%0,%1,%2,%3}, {%4,%5,%6,%7}, {%8,%9}, {%0,%1,%2,%3};"
                : "+f"(acc[t].x), "+f"(acc[t].y), "+f"(acc[t].z), "+f"(acc[t].w)
                : "r"(a0), "r"(a1), "r"(a2), "r"(a3), "r"(b0), "r"(b1));
        }
    }

    const int r0 = rowbase + wr + gid;
    const int r1 = r0 + 8;
    float d0 = 1.0f, d1 = 1.0f;
    if (L == 1) {
        d0 = (r0 < N_NODES) ? g_dinv[r0] : 0.0f;
        d1 = (r1 < N_NODES) ? g_dinv[r1] : 0.0f;
    }
    #pragma unroll
    for (int t = 0; t < 4; t++) {
        int slot = (wc >> 1) + t * 4 + tg;
        if (r0 < N_NODES)
            dst[r0 * 32 + slot] = __floats2half2_rn(acc[t].x * d0, acc[t].y * d0);
        if (r1 < N_NODES)
            dst[r1 * 32 + slot] = __floats2half2_rn(acc[t].z * d1, acc[t].w * d1);
    }
}

// ---------------------------------------------------------------------------
// z[node] = relu( dinv[node] * (hs[node] + sum_{neigh} hs[s]) + b )
// FUSE_OUT == 0: reads g_hsh, writes g_z.
// FUSE_OUT == 1: reads g_hsh2, fused linear readout, restores indeg invariant.
// ---------------------------------------------------------------------------
template <int FUSE_OUT>
__global__ void __launch_bounds__(256) k_aggregate(const float* __restrict__ b,
                                                   const float* __restrict__ Wo,
                                                   const float* __restrict__ bo,
                                                   float* __restrict__ out) {
    const int t = blockIdx.x * blockDim.x + threadIdx.x;
    const int node = t >> 5;
    if (node >= N_NODES) return;
    const int lane = t & 31;

    const __half2* __restrict__ hs = (FUSE_OUT == 0) ? g_hsh : g_hsh2;

    float2 acc = __half22float2(hs[node * 32 + lane]);  // self loop

    const int deg = g_indeg[node];
    int e   = g_start[node] + g_boff[node >> 9];
    const int end = e + deg;

    for (; e + 8 <= end; e += 8) {
        int s0 = __ldg(&g_csr[e]);
        int s1 = __ldg(&g_csr[e + 1]);
        int s2 = __ldg(&g_csr[e + 2]);
        int s3 = __ldg(&g_csr[e + 3]);
        int s4 = __ldg(&g_csr[e + 4]);
        int s5 = __ldg(&g_csr[e + 5]);
        int s6 = __ldg(&g_csr[e + 6]);
        int s7 = __ldg(&g_csr[e + 7]);
        float2 v0 = __half22float2(__ldg(&hs[s0 * 32 + lane]));
        float2 v1 = __half22float2(__ldg(&hs[s1 * 32 + lane]));
        float2 v2 = __half22float2(__ldg(&hs[s2 * 32 + lane]));
        float2 v3 = __half22float2(__ldg(&hs[s3 * 32 + lane]));
        float2 v4 = __half22float2(__ldg(&hs[s4 * 32 + lane]));
        float2 v5 = __half22float2(__ldg(&hs[s5 * 32 + lane]));
        float2 v6 = __half22float2(__ldg(&hs[s6 * 32 + lane]));
        float2 v7 = __half22float2(__ldg(&hs[s7 * 32 + lane]));
        acc.x += ((v0.x + v1.x) + (v2.x + v3.x)) + ((v4.x + v5.x) + (v6.x + v7.x));
        acc.y += ((v0.y + v1.y) + (v2.y + v3.y)) + ((v4.y + v5.y) + (v6.y + v7.y));
    }
    for (; e < end; e++) {
        int s = __ldg(&g_csr[e]);
        float2 v = __half22float2(__ldg(&hs[s * 32 + lane]));
        acc.x += v.x; acc.y += v.y;
    }

    const float di = g_dinv[node];
    const int c = lane * 2;
    float2 bb = *(const float2*)(b + c);
    float zx = fmaxf(acc.x * di + bb.x, 0.0f);
    float zy = fmaxf(acc.y * di + bb.y, 0.0f);

    if constexpr (FUSE_OUT == 0) {
        *(float2*)(g_z + node * 64 + c) = make_float2(zx, zy);
    } else {
        float2 w = *(const float2*)(Wo + c);
        float sum = zx * w.x + zy * w.y;
        #pragma unroll
        for (int off = 16; off; off >>= 1)
            sum += __shfl_down_sync(0xffffffff, sum, off);
        if (lane == 0) {
            out[node] = sum + bo[0];
            g_indeg[node] = 0;       // restore invariant for next call
        }
    }
}

// ---------------------------------------------------------------------------
extern "C" void kernel_launch(void* const* d_in, const int* in_sizes, int n_in,
                              void* d_out, int out_size) {
    const float* h  = (const float*)d_in[0];
    const int*   ei = (const int*)d_in[1];   // int32 [2,E]
    const float* W1 = (const float*)d_in[2];
    const float* b1 = (const float*)d_in[3];
    const float* W2 = (const float*)d_in[4];
    const float* b2 = (const float*)d_in[5];
    const float* Wo = (const float*)d_in[6];
    const float* bo = (const float*)d_in[7];
    float* out = (float*)d_out;

    cudaStream_t s2;
    cudaStreamCreateWithFlags(&s2, cudaStreamNonBlocking);
    cudaEvent_t eFork, eScan, eJoin;
    cudaEventCreateWithFlags(&eFork, cudaEventDisableTiming);
    cudaEventCreateWithFlags(&eScan, cudaEventDisableTiming);
    cudaEventCreateWithFlags(&eJoin, cudaEventDisableTiming);

    // s2: gemm0 (raw h@W1, zero deps) at t=0.
    cudaEventRecord(eFork, 0);
    cudaStreamWaitEvent(s2, eFork, 0);
    k_gemm<0><<<(N_NODES + 63) / 64, 256, 0, s2>>>(h, W1);

    // main: CSR build (no init kernel — invariant maintained by consumers).
    k_count<<<(N_EDGES + 255) / 256, 256>>>(ei);
    k_scan<<<N_SCANB, SCAN_B>>>();
    cudaEventRecord(eScan, 0);

    // s2: scale pass (after gemm0 in-stream + scan's dinv); overlaps k_fill.
    cudaStreamWaitEvent(s2, eScan, 0);
    k_scale<<<(N_NODES * 8 + 255) / 256, 256, 0, s2>>>();
    cudaEventRecord(eJoin, s2);

    k_fill<<<(N_EDGES + 255) / 256, 256>>>(ei);

    // Serial tail (launch count beats concurrency tricks at this budget).
    cudaStreamWaitEvent(0, eJoin, 0);
    k_aggregate<0><<<(N_NODES * 32 + 255) / 256, 256>>>(b1, nullptr, nullptr, nullptr);
    k_gemm<1><<<(N_NODES + 63) / 64, 256>>>(nullptr, W2);
    k_aggregate<1><<<(N_NODES * 32 + 255) / 256, 256>>>(b2, Wo, bo, out);

    cudaEventDestroy(eFork);
    cudaEventDestroy(eScan);
    cudaEventDestroy(eJoin);
    cudaStreamDestroy(s2);
}

// round 17
// speedup vs baseline: 1.0814x; 1.0456x over previous
#include <cuda_runtime.h>
#include <cuda_fp16.h>

#define N_NODES 100000
#define N_EDGES 1600000
#define F 64
#define SCAN_B 512
#define N_SCANB ((N_NODES + SCAN_B - 1) / SCAN_B)   // 196

// GEMM tile geometry
#define GEMM_ROWS 128
#define GEMM_GRID ((N_NODES + GEMM_ROWS - 1) / GEMM_ROWS)   // 782
#define XP 68   // Xs pitch (mod 32 == 4 -> conflict-free A-frag gather)
#define WP 72   // Ws pitch (mod 32 == 8 -> conflict-free B-frag gather)
#define GEMM_SMEM ((GEMM_ROWS * XP + 64 * WP) * 4)          // 53248 B

// ---- scratch (static __device__, zero-initialized at module load; each call
//      restores the zeros it consumes -> invariant holds across graph replays)
__device__ int     g_done;                 // scan completion counter (self-resetting)
__device__ int     g_indeg[N_NODES];       // re-zeroed by k_aggregate<1> after last use
__device__ int     g_start[N_NODES];
__device__ int     g_cur[N_NODES];
__device__ int     g_bsum[SCAN_B];
__device__ int     g_boff[SCAN_B];
__device__ float   g_dinv[N_NODES];
__device__ int     g_csr[N_EDGES];
__device__ __half2 g_hsh [N_NODES * 32];   // layer-1 messages (fp16)
__device__ __half2 g_hsh2[N_NODES * 32];   // layer-2 messages (fp16)
__device__ __half2 g_zh  [N_NODES * 32];   // layer-1 activations (fp16: tf32 has the
                                           // same 10-bit mantissa, so no extra loss)

// ---------------------------------------------------------------------------
__global__ void k_count(const int* __restrict__ ei) {
    int e = blockIdx.x * blockDim.x + threadIdx.x;
    if (e >= N_EDGES) return;
    int d = ei[N_EDGES + e];
    if ((unsigned)d < N_NODES) atomicAdd(&g_indeg[d], 1);
}

// ---------------------------------------------------------------------------
// Shuffle-based inclusive block scan (512 threads).
// ---------------------------------------------------------------------------
__device__ __forceinline__ int block_scan_incl(int v, int tid, int* warpsum) {
    const int lane = tid & 31, w = tid >> 5;
    int x = v;
    #pragma unroll
    for (int s = 1; s < 32; s <<= 1) {
        int t = __shfl_up_sync(0xffffffff, x, s);
        if (lane >= s) x += t;
    }
    if (lane == 31) warpsum[w] = x;
    __syncthreads();
    if (w == 0) {
        int y = (lane < 16) ? warpsum[lane] : 0;
        #pragma unroll
        for (int s = 1; s < 16; s <<= 1) {
            int t = __shfl_up_sync(0xffffffff, y, s);
            if (lane >= s) y += t;
        }
        if (lane < 16) warpsum[lane] = y;
    }
    __syncthreads();
    return x + (w > 0 ? warpsum[w - 1] : 0);
}

__global__ void __launch_bounds__(SCAN_B) k_scan() {
    __shared__ int ws[16];
    __shared__ int amLast;
    const int tid = threadIdx.x;
    int i = blockIdx.x * SCAN_B + tid;
    int v = (i < N_NODES) ? g_indeg[i] : 0;
    int incl = block_scan_incl(v, tid, ws);
    if (i < N_NODES) {
        int ex = incl - v;
        g_start[i] = ex;
        g_cur[i]   = ex;
        g_dinv[i]  = rsqrtf((float)(v + 1));   // +1 self loop
    }
    if (tid == SCAN_B - 1) g_bsum[blockIdx.x] = incl;
    __threadfence();
    __syncthreads();
    if (tid == 0)
        amLast = (atomicAdd(&g_done, 1) == (int)gridDim.x - 1);
    __syncthreads();
    if (amLast) {
        __threadfence();
        int bv = (tid < N_SCANB) ? g_bsum[tid] : 0;
        int bincl = block_scan_incl(bv, tid, ws);
        if (tid < N_SCANB) g_boff[tid] = bincl - bv;
        if (tid == 0) g_done = 0;   // restore invariant for next call
    }
}

__global__ void k_fill(const int* __restrict__ ei) {
    int e = blockIdx.x * blockDim.x + threadIdx.x;
    if (e >= N_EDGES) return;
    int s = ei[e];
    int d = ei[N_EDGES + e];
    if ((unsigned)s < N_NODES && (unsigned)d < N_NODES) {
        int slot = atomicAdd(&g_cur[d], 1) + g_boff[d >> 9];
        if ((unsigned)slot < N_EDGES) g_csr[slot] = s;
    }
}

// ---------------------------------------------------------------------------
// Per-node scale pass: g_hsh[row] *= dinv[row]; overlapped with k_fill on s2.
// ---------------------------------------------------------------------------
__global__ void __launch_bounds__(256) k_scale() {
    int i = blockIdx.x * blockDim.x + threadIdx.x;          // uint4 index
    if (i >= N_NODES * 8) return;
    int row = i >> 3;
    __half2 dh = __float2half2_rn(g_dinv[row]);
    uint4 v = *(const uint4*)&g_hsh[(size_t)i * 4];
    __half2* p = (__half2*)&v;
    p[0] = __hmul2(p[0], dh);
    p[1] = __hmul2(p[1], dh);
    p[2] = __hmul2(p[2], dh);
    p[3] = __hmul2(p[3], dh);
    *(uint4*)&g_hsh[(size_t)i * 4] = v;
}

// ---------------------------------------------------------------------------
// Tensor-core GEMM (tf32 m16n8k8), fp16 store. 128x64 tile, 256 thr, 8 warps;
// warp w owns rows [w*16, w*16+16) x all 64 cols (8 m16n8 tiles, shared A-frag).
//   L == 0: X = raw h (fp32)  -> g_hsh, raw product (no dinv; forked at t=0)
//   L == 1: X = g_zh (fp16)   -> g_hsh2, dinv epilogue
// Dynamic smem: [Xs 128*XP u32][Ws 64*WP u32] = 53248 B.
// ---------------------------------------------------------------------------
__device__ __forceinline__ unsigned f2tf32(float f) {
    unsigned r;
    asm("cvt.rna.tf32.f32 %0, %1;" : "=r"(r) : "f"(f));
    return r;
}

template <int L>
__global__ void __launch_bounds__(256) k_gemm(const float* __restrict__ Xin,
                                              const float* __restrict__ W) {
    extern __shared__ unsigned smem[];
    unsigned* Xs = smem;                       // [GEMM_ROWS][XP]
    unsigned* Ws = smem + GEMM_ROWS * XP;      // [64][WP]

    __half2* __restrict__ dst = (L == 0) ? g_hsh : g_hsh2;

    const int tid = threadIdx.x;
    const int rowbase = blockIdx.x * GEMM_ROWS;

    // Stage W (64x64 fp32 -> tf32), float4 loads: 1024 float4 / 256 thr.
    #pragma unroll
    for (int i = tid; i < 1024; i += 256) {
        int k = i >> 4, n4 = (i & 15) * 4;
        float4 v = *(const float4*)&W[k * 64 + n4];
        unsigned* p = &Ws[k * WP + n4];
        p[0] = f2tf32(v.x); p[1] = f2tf32(v.y); p[2] = f2tf32(v.z); p[3] = f2tf32(v.w);
    }

    // Stage X -> tf32.
    if (L == 0) {
        // fp32 input: 128*64 floats = 2048 float4.
        #pragma unroll
        for (int i = tid; i < 2048; i += 256) {
            int r = i >> 4, c4 = (i & 15) * 4;
            int row = rowbase + r;
            float4 v = (row < N_NODES) ? *(const float4*)&Xin[row * 64 + c4]
                                       : make_float4(0.f, 0.f, 0.f, 0.f);
            unsigned* p = &Xs[r * XP + c4];
            p[0] = f2tf32(v.x); p[1] = f2tf32(v.y); p[2] = f2tf32(v.z); p[3] = f2tf32(v.w);
        }
    } else {
        // fp16 input (g_zh): 128 rows * 8 uint4 (8 halves each) = 1024 uint4.
        #pragma unroll
        for (int i = tid; i < 1024; i += 256) {
            int r = i >> 3, c8 = (i & 7) * 8;
            int row = rowbase + r;
            uint4 v = make_uint4(0u, 0u, 0u, 0u);
            if (row < N_NODES) v = *(const uint4*)&g_zh[row * 32 + (i & 7) * 4];
            const __half2* hp = (const __half2*)&v;
            unsigned* p = &Xs[r * XP + c8];
            #pragma unroll
            for (int j = 0; j < 4; j++) {
                float2 f = __half22float2(hp[j]);
                p[j * 2]     = f2tf32(f.x);
                p[j * 2 + 1] = f2tf32(f.y);
            }
        }
    }
    __syncthreads();

    const int warp = tid >> 5;
    const int lane = tid & 31;
    const int gid  = lane >> 2;
    const int tg   = lane & 3;
    const int wr   = warp * 16;     // warp row base (0..112)

    float4 acc[8];
    #pragma unroll
    for (int t = 0; t < 8; t++) acc[t] = make_float4(0.f, 0.f, 0.f, 0.f);

    #pragma unroll
    for (int kb = 0; kb < 64; kb += 8) {
        const unsigned* xrow = &Xs[(wr + gid) * XP + kb + tg];
        unsigned a0 = xrow[0];
        unsigned a1 = xrow[8 * XP];
        unsigned a2 = xrow[4];
        unsigned a3 = xrow[8 * XP + 4];
        #pragma unroll
        for (int t = 0; t < 8; t++) {
            const unsigned* wcol = &Ws[(kb + tg) * WP + t * 8 + gid];
            unsigned b0 = wcol[0];
            unsigned b1 = wcol[4 * WP];
            asm volatile(
                "mma.sync.aligned.m16n8k8.row.col.f32.tf32.tf32.f32 "
                "{%0,%1,%2,%3}, {%4,%5,%6,%7}, {%8,%9}, {%0,%1,%2,%3};"
                : "+f"(acc[t].x), "+f"(acc[t].y), "+f"(acc[t].z), "+f"(acc[t].w)
                : "r"(a0), "r"(a1), "r"(a2), "r"(a3), "r"(b0), "r"(b1));
        }
    }

    const int r0 = rowbase + wr + gid;
    const int r1 = r0 + 8;
    float d0 = 1.0f, d1 = 1.0f;
    if (L == 1) {
        d0 = (r0 < N_NODES) ? g_dinv[r0] : 0.0f;
        d1 = (r1 < N_NODES) ? g_dinv[r1] : 0.0f;
    }
    #pragma unroll
    for (int t = 0; t < 8; t++) {
        int slot = t * 4 + tg;      // half2 slot = col/2, cols t*8+2tg(+1)
        if (r0 < N_NODES)
            dst[r0 * 32 + slot] = __floats2half2_rn(acc[t].x * d0, acc[t].y * d0);
        if (r1 < N_NODES)
            dst[r1 * 32 + slot] = __floats2half2_rn(acc[t].z * d1, acc[t].w * d1);
    }
}

// ---------------------------------------------------------------------------
// z[node] = relu( dinv[node] * (hs[node] + sum_{neigh} hs[s]) + b )
// FUSE_OUT == 0: reads g_hsh, writes g_zh (fp16).
// FUSE_OUT == 1: reads g_hsh2, fused linear readout, restores indeg invariant.
// ---------------------------------------------------------------------------
template <int FUSE_OUT>
__global__ void __launch_bounds__(256) k_aggregate(const float* __restrict__ b,
                                                   const float* __restrict__ Wo,
                                                   const float* __restrict__ bo,
                                                   float* __restrict__ out) {
    const int t = blockIdx.x * blockDim.x + threadIdx.x;
    const int node = t >> 5;
    if (node >= N_NODES) return;
    const int lane = t & 31;

    const __half2* __restrict__ hs = (FUSE_OUT == 0) ? g_hsh : g_hsh2;

    float2 acc = __half22float2(hs[node * 32 + lane]);  // self loop

    const int deg = g_indeg[node];
    int e   = g_start[node] + g_boff[node >> 9];
    const int end = e + deg;

    for (; e + 8 <= end; e += 8) {
        int s0 = __ldg(&g_csr[e]);
        int s1 = __ldg(&g_csr[e + 1]);
        int s2 = __ldg(&g_csr[e + 2]);
        int s3 = __ldg(&g_csr[e + 3]);
        int s4 = __ldg(&g_csr[e + 4]);
        int s5 = __ldg(&g_csr[e + 5]);
        int s6 = __ldg(&g_csr[e + 6]);
        int s7 = __ldg(&g_csr[e + 7]);
        float2 v0 = __half22float2(__ldg(&hs[s0 * 32 + lane]));
        float2 v1 = __half22float2(__ldg(&hs[s1 * 32 + lane]));
        float2 v2 = __half22float2(__ldg(&hs[s2 * 32 + lane]));
        float2 v3 = __half22float2(__ldg(&hs[s3 * 32 + lane]));
        float2 v4 = __half22float2(__ldg(&hs[s4 * 32 + lane]));
        float2 v5 = __half22float2(__ldg(&hs[s5 * 32 + lane]));
        float2 v6 = __half22float2(__ldg(&hs[s6 * 32 + lane]));
        float2 v7 = __half22float2(__ldg(&hs[s7 * 32 + lane]));
        acc.x += ((v0.x + v1.x) + (v2.x + v3.x)) + ((v4.x + v5.x) + (v6.x + v7.x));
        acc.y += ((v0.y + v1.y) + (v2.y + v3.y)) + ((v4.y + v5.y) + (v6.y + v7.y));
    }
    for (; e < end; e++) {
        int s = __ldg(&g_csr[e]);
        float2 v = __half22float2(__ldg(&hs[s * 32 + lane]));
        acc.x += v.x; acc.y += v.y;
    }

    const float di = g_dinv[node];
    const int c = lane * 2;
    float2 bb = *(const float2*)(b + c);
    float zx = fmaxf(acc.x * di + bb.x, 0.0f);
    float zy = fmaxf(acc.y * di + bb.y, 0.0f);

    if constexpr (FUSE_OUT == 0) {
        g_zh[node * 32 + lane] = __floats2half2_rn(zx, zy);
    } else {
        float2 w = *(const float2*)(Wo + c);
        float sum = zx * w.x + zy * w.y;
        #pragma unroll
        for (int off = 16; off; off >>= 1)
            sum += __shfl_down_sync(0xffffffff, sum, off);
        if (lane == 0) {
            out[node] = sum + bo[0];
            g_indeg[node] = 0;       // restore invariant for next call
        }
    }
}

// ---------------------------------------------------------------------------
extern "C" void kernel_launch(void* const* d_in, const int* in_sizes, int n_in,
                              void* d_out, int out_size) {
    const float* h  = (const float*)d_in[0];
    const int*   ei = (const int*)d_in[1];   // int32 [2,E]
    const float* W1 = (const float*)d_in[2];
    const float* b1 = (const float*)d_in[3];
    const float* W2 = (const float*)d_in[4];
    const float* b2 = (const float*)d_in[5];
    const float* Wo = (const float*)d_in[6];
    const float* bo = (const float*)d_in[7];
    float* out = (float*)d_out;

    cudaFuncSetAttribute(k_gemm<0>, cudaFuncAttributeMaxDynamicSharedMemorySize, GEMM_SMEM);
    cudaFuncSetAttribute(k_gemm<1>, cudaFuncAttributeMaxDynamicSharedMemorySize, GEMM_SMEM);

    cudaStream_t s2;
    cudaStreamCreateWithFlags(&s2, cudaStreamNonBlocking);
    cudaEvent_t eFork, eScan, eJoin;
    cudaEventCreateWithFlags(&eFork, cudaEventDisableTiming);
    cudaEventCreateWithFlags(&eScan, cudaEventDisableTiming);
    cudaEventCreateWithFlags(&eJoin, cudaEventDisableTiming);

    // s2: gemm0 (raw h@W1, zero deps) at t=0.
    cudaEventRecord(eFork, 0);
    cudaStreamWaitEvent(s2, eFork, 0);
    k_gemm<0><<<GEMM_GRID, 256, GEMM_SMEM, s2>>>(h, W1);

    // main: CSR build (no init kernel — invariant maintained by consumers).
    k_count<<<(N_EDGES + 255) / 256, 256>>>(ei);
    k_scan<<<N_SCANB, SCAN_B>>>();
    cudaEventRecord(eScan, 0);

    // s2: scale pass (after gemm0 in-stream + scan's dinv); overlaps k_fill.
    cudaStreamWaitEvent(s2, eScan, 0);
    k_scale<<<(N_NODES * 8 + 255) / 256, 256, 0, s2>>>();
    cudaEventRecord(eJoin, s2);

    k_fill<<<(N_EDGES + 255) / 256, 256>>>(ei);

    // Serial tail.
    cudaStreamWaitEvent(0, eJoin, 0);
    k_aggregate<0><<<(N_NODES * 32 + 255) / 256, 256>>>(b1, nullptr, nullptr, nullptr);
    k_gemm<1><<<GEMM_GRID, 256, GEMM_SMEM>>>(nullptr, W2);
    k_aggregate<1><<<(N_NODES * 32 + 255) / 256, 256>>>(b2, Wo, bo, out);

    cudaEventDestroy(eFork);
    cudaEventDestroy(eScan);
    cudaEventDestroy(eJoin);
    cudaStreamDestroy(s2);
}